// round 15
// baseline (speedup 1.0000x reference)
#include <cuda_runtime.h>
#include <cuda_bf16.h>

#define N_ATOMS 8192
#define NT 85
#define BINS 28
#define BINS2 29                                  // 28 real bins + zero pad bin
#define ROWSZ2 (NT * BINS2)                       // 2465
#define TILE 128
#define T_TILES (N_ATOMS / TILE)                  // 64
#define NTILEPAIRS (T_TILES * (T_TILES + 1) / 2)  // 2080
#define NUNITS (NTILEPAIRS * 4)                   // 8320 quarter-tile units
#define BLOCKS_PER_SM 10
#define GRID_PERSIST (148 * BLOCKS_PER_SM)        // 1480
#define THREADS 128
#define LUT_SIZE (NT * NT * BINS2)                // 209525
#define SORT_BLOCKS 16                            // 16 x 512 = 8192 atoms
#define LUT_GRID ((LUT_SIZE + 2047) / 2048)       // 103 blocks, 4 entries/thread
#define PREP_GRID (SORT_BLOCKS + LUT_GRID)        // 119 blocks — all co-resident
#define NSLOTS 32
#define INV07 1.42857142857142857f

typedef unsigned long long u64;

#define F32X2_ADD(d, a, b) \
    asm("add.rn.f32x2 %0, %1, %2;" : "=l"(d) : "l"(a), "l"(b))
#define F32X2_MUL(d, a, b) \
    asm("mul.rn.f32x2 %0, %1, %2;" : "=l"(d) : "l"(a), "l"(b))
#define F32X2_FMA(d, a, b, c) \
    asm("fma.rn.f32x2 %0, %1, %2, %3;" : "=l"(d) : "l"(a), "l"(b), "l"(c))

__device__ __forceinline__ u64 pack2(float lo, float hi) {
    return __double_as_longlong(
        __hiloint2double(__float_as_int(hi), __float_as_int(lo)));
}
__device__ __forceinline__ float lo_f(u64 v) {
    return __int_as_float(__double2loint(__longlong_as_double(v)));
}
__device__ __forceinline__ float hi_f(u64 v) {
    return __int_as_float(__double2hiint(__longlong_as_double(v)));
}
__device__ __forceinline__ int lo_i(u64 v) {
    return __double2loint(__longlong_as_double(v));
}
__device__ __forceinline__ int hi_i(u64 v) {
    return __double2hiint(__longlong_as_double(v));
}

// Slope-intercept LUT with zero pad bin 28 (beyond 19.6A cutoff -> exactly 0).
__device__ float2 g_lut[LUT_SIZE];
// Atoms bucket-sorted by type, coords pre-scaled by 1/0.7; j-side AoS view.
__device__ float4 g_atoms[N_ATOMS];
// i-side pair-packed view: per atom pair 8 floats [x0,x1,y0,y1,z0,z1,w0,w1].
__device__ double2 g_ipairs[N_ATOMS];
__device__ int    g_tij[NTILEPAIRS];              // tile b -> (ti<<8 | tj)
__device__ double   g_sums[NSLOTS];
__device__ unsigned g_count;
// Sort pipeline state — module-load zeroed; the last sort block re-zeros it
// every run, so every graph replay sees a clean state.
__device__ int      g_hist[NT];
__device__ int      g_cursor[NT];
__device__ unsigned g_histdone;
__device__ unsigned g_flag;
__device__ unsigned g_k2done;

// Fused prep: blocks [0, SORT_BLOCKS) run the sort pipeline (hist -> scan ->
// scatter -> self-clean); blocks [SORT_BLOCKS, PREP_GRID) build the LUT (4
// entries/thread), the tile decode table, and zero the accumulators.
// PREP_GRID=119 <= 148 SMs: every block is resident before any spin, so the
// intra-grid waits cannot deadlock.
__global__ void prep_kernel(const float* __restrict__ pot,
                            const float* __restrict__ coords,
                            const int*  __restrict__ res_ids,
                            const int*  __restrict__ type_indices) {
    int tid = threadIdx.x;

    if (blockIdx.x >= SORT_BLOCKS) {
        // ---------- LUT / tij / accumulator-zero role ----------
        int lb   = blockIdx.x - SORT_BLOCKS;
        int base = lb * 2048 + tid * 4;           // 4 consecutive entries (MLP 8)
        if (lb == 0 && tid <= NSLOTS) {
            if (tid < NSLOTS) g_sums[tid] = 0.0;
            else g_count = 0u;
        }
#pragma unroll
        for (int k = 0; k < 4; ++k) {
            int idx = base + k;
            if (idx < LUT_SIZE) {
                int t12 = idx / BINS2;
                int d   = idx - t12 * BINS2;
                float2 v;
                if (d >= BINS) {
                    v = make_float2(0.0f, 0.0f);  // pad bin
                } else {
                    float e0 = pot[t12 * BINS + d];
                    float e1 = (d == BINS - 1) ? e0 : pot[t12 * BINS + d + 1];
                    float B  = e1 - e0;
                    v = make_float2(fmaf(-(float)d, B, e0), B);
                }
                g_lut[idx] = v;
            }
        }
        int b = lb * 512 + tid;                   // tile decode table
        if (b < NTILEPAIRS) {
            int ti = 0, acc = 0;
            while (acc + (T_TILES - ti) <= b) { acc += T_TILES - ti; ++ti; }
            g_tij[b] = (ti << 8) | (ti + (b - acc));
        }
        return;
    }

    // ---------- sort role (blocks 0..15, one atom per thread) ----------
    __shared__ int sh[NT];
    int i = blockIdx.x * 512 + tid;
    int t = type_indices[i];

    for (int k = tid; k < NT; k += 512) sh[k] = 0;
    __syncthreads();
    atomicAdd(&sh[t], 1);
    __syncthreads();
    for (int k = tid; k < NT; k += 512)
        if (sh[k]) atomicAdd(&g_hist[k], sh[k]);
    __syncthreads();
    if (tid == 0) {
        __threadfence();
        atomicAdd(&g_histdone, 1u);
    }

    if (blockIdx.x == 0 && tid == 0) {            // scan after all hists land
        while (atomicAdd(&g_histdone, 0u) < SORT_BLOCKS) __nanosleep(32);
        __threadfence();                          // acquire hist writes
        int run = 0;
        for (int k = 0; k < NT; ++k) {
            int c = atomicAdd(&g_hist[k], 0);     // coherent L2 read
            g_cursor[k] = run; run += c;
        }
        __threadfence();
        atomicExch(&g_flag, 1u);
    }
    if (tid == 0) {
        while (atomicAdd(&g_flag, 0u) == 0u) __nanosleep(32);
        __threadfence();                          // acquire cursor writes
    }
    __syncthreads();

    int pos = atomicAdd(&g_cursor[t], 1);
    float x = coords[3 * i + 0] * INV07;
    float y = coords[3 * i + 1] * INV07;
    float z = coords[3 * i + 2] * INV07;
    int   w = (res_ids[i] << 18) | (t * ROWSZ2);
    g_atoms[pos] = make_float4(x, y, z, __int_as_float(w));
    float* f = (float*)g_ipairs;                  // pair-packed mirror
    int p = pos >> 1, s = pos & 1;
    f[8 * p + 0 + s] = x;
    f[8 * p + 2 + s] = y;
    f[8 * p + 4 + s] = z;
    f[8 * p + 6 + s] = __int_as_float(w);

    __syncthreads();
    if (tid == 0) {                               // last sort block cleans state
        unsigned done = atomicAdd(&g_k2done, 1u);
        if (done == SORT_BLOCKS - 1) {
            for (int k = 0; k < NT; ++k) g_hist[k] = 0;
            g_histdone = 0u;
            g_flag = 0u;
            g_k2done = 0u;
            __threadfence();
        }
    }
}

// 32 i atoms (16 packed pairs) vs this thread's j atom.
template <bool DIAG>
__device__ __forceinline__ float chunk_sum(const double2* __restrict__ ib,
                                           u64 jxn, u64 jyn, u64 jzn,
                                           int loB, const float2* __restrict__ jlut,
                                           int lim) {
    float acc0 = 0.0f, acc1 = 0.0f;
#pragma unroll
    for (int k = 0; k < 16; ++k) {
        double2 v0 = __ldg(&ib[2 * k + 0]);       // (x0x1, y0y1) uniform LDG.128
        double2 v1 = __ldg(&ib[2 * k + 1]);       // (z0z1, w0w1)
        u64 xs = __double_as_longlong(v0.x);
        u64 ys = __double_as_longlong(v0.y);
        u64 zs = __double_as_longlong(v1.x);
        u64 ws = __double_as_longlong(v1.y);

        u64 dx2, dy2, dz2, d2p;
        F32X2_ADD(dx2, xs, jxn);                  // (xi - xj) x2
        F32X2_ADD(dy2, ys, jyn);
        F32X2_ADD(dz2, zs, jzn);
        F32X2_MUL(d2p, dx2, dx2);
        F32X2_FMA(d2p, dy2, dy2, d2p);
        F32X2_FMA(d2p, dz2, dz2, d2p);            // (d/0.7)^2 for both pairs

        {   // pair 0 (i local = 2k); self-pair NaN routes to pad bin, masked out
            float d2 = lo_f(d2p);
            int   pi = lo_i(ws);
            float ds = d2 * rsqrtf(d2);
            float dsc = fminf(ds, 28.0f);         // NaN -> 28 -> (0,0) pad
            int   d0 = (int)dsc;
            float2 e = __ldg(&jlut[(pi & 0x3FFFF) + d0]);
            bool ok = (unsigned)(pi - loB) >= (5u << 18);   // sep > 2
            if (DIAG) ok &= (2 * k < lim);
            float val = fmaf(e.y, ds, e.x);
            if (ok) acc0 += val;
        }
        {   // pair 1 (i local = 2k+1)
            float d2 = hi_f(d2p);
            int   pi = hi_i(ws);
            float ds = d2 * rsqrtf(d2);
            float dsc = fminf(ds, 28.0f);
            int   d0 = (int)dsc;
            float2 e = __ldg(&jlut[(pi & 0x3FFFF) + d0]);
            bool ok = (unsigned)(pi - loB) >= (5u << 18);
            if (DIAG) ok &= (2 * k + 1 < lim);
            float val = fmaf(e.y, ds, e.x);
            if (ok) acc1 += val;
        }
    }
    return acc0 + acc1;
}

__global__ __launch_bounds__(THREADS, BLOCKS_PER_SM)
void dfire_kernel(float* __restrict__ out) {
    __shared__ double s_warp[THREADS / 32];
    const int tid = threadIdx.x;

    float acc = 0.0f;

    for (int u = blockIdx.x; u < NUNITS; u += GRID_PERSIST) {
        int b  = u >> 2;
        int q  = u & 3;
        int tt = g_tij[b];
        int ti = tt >> 8;
        int tj = tt & 255;

        const double2* ib = g_ipairs + (ti * TILE + q * 32);
        float4 aj = g_atoms[tj * TILE + tid];     // coalesced LDG.128

        int pj    = __float_as_int(aj.w);
        int jres  = pj >> 18;
        int jtype = (pj & 0x3FFFF) / ROWSZ2;
        int loB   = (jres - 2) << 18;
        const float2* jlut = g_lut + jtype * BINS2;
        u64 jxn = pack2(-aj.x, -aj.x);
        u64 jyn = pack2(-aj.y, -aj.y);
        u64 jzn = pack2(-aj.z, -aj.z);

        if (ti == tj) {
            int lim = tid - q * 32;               // i_local < j_local
            acc += chunk_sum<true >(ib, jxn, jyn, jzn, loB, jlut, lim);
        } else {
            acc += chunk_sum<false>(ib, jxn, jyn, jzn, loB, jlut, 0);
        }
    }

#pragma unroll
    for (int off = 16; off > 0; off >>= 1)
        acc += __shfl_xor_sync(0xFFFFFFFFu, acc, off);
    if ((tid & 31) == 0) s_warp[tid >> 5] = (double)acc;
    __syncthreads();

    if (tid == 0) {
        double s = s_warp[0] + s_warp[1] + s_warp[2] + s_warp[3];
        atomicAdd(&g_sums[blockIdx.x & (NSLOTS - 1)], s);
        __threadfence();
        unsigned done = atomicAdd(&g_count, 1u);
        if (done == GRID_PERSIST - 1) {           // last block finalizes
            double tot = 0.0;
#pragma unroll
            for (int k = 0; k < NSLOTS; ++k)
                tot += atomicAdd(&g_sums[k], 0.0);
            out[0] = (float)tot;
        }
    }
}

extern "C" void kernel_launch(void* const* d_in, const int* in_sizes, int n_in,
                              void* d_out, int out_size) {
    // Input order: coords, pot_tensor, res_ids, type_indices, i_idx, j_idx
    const float* coords       = (const float*)d_in[0];
    const float* pot_tensor   = (const float*)d_in[1];
    const int*   res_ids      = (const int*)d_in[2];
    const int*   type_indices = (const int*)d_in[3];
    // i_idx / j_idx are the deterministic triu indices; regenerated implicitly.
    (void)in_sizes; (void)n_in; (void)out_size;
    float* out = (float*)d_out;

    prep_kernel<<<PREP_GRID, 512>>>(pot_tensor, coords, res_ids, type_indices);
    dfire_kernel<<<GRID_PERSIST, THREADS>>>(out);
}

// round 16
// speedup vs baseline: 1.3461x; 1.3461x over previous
#include <cuda_runtime.h>
#include <cuda_bf16.h>

#define N_ATOMS 8192
#define NT 85
#define BINS 28
#define BINS2 29                                  // 28 real bins + zero pad bin
#define ROWSZ2 (NT * BINS2)                       // 2465
#define TILE 128
#define T_TILES (N_ATOMS / TILE)                  // 64
#define NTILEPAIRS (T_TILES * (T_TILES + 1) / 2)  // 2080
#define NUNITS (NTILEPAIRS * 4)                   // 8320 quarter-tile units
#define BLOCKS_PER_SM 10
#define GRID_PERSIST (148 * BLOCKS_PER_SM)        // 1480
#define THREADS 128
#define LUT_SIZE (NT * NT * BINS2)                // 209525
#define SORT_BLOCKS 16                            // 16 x 512 = 8192 atoms
#define LUT_GRID ((LUT_SIZE + 2047) / 2048)       // 103 blocks, 4 entries/thread
#define PREP_GRID (SORT_BLOCKS + LUT_GRID)        // 119 blocks — all co-resident
#define NSLOTS 32
#define INV07 1.42857142857142857f

typedef unsigned long long u64;

#define F32X2_ADD(d, a, b) \
    asm("add.rn.f32x2 %0, %1, %2;" : "=l"(d) : "l"(a), "l"(b))
#define F32X2_MUL(d, a, b) \
    asm("mul.rn.f32x2 %0, %1, %2;" : "=l"(d) : "l"(a), "l"(b))
#define F32X2_FMA(d, a, b, c) \
    asm("fma.rn.f32x2 %0, %1, %2, %3;" : "=l"(d) : "l"(a), "l"(b), "l"(c))

__device__ __forceinline__ u64 pack2(float lo, float hi) {
    return __double_as_longlong(
        __hiloint2double(__float_as_int(hi), __float_as_int(lo)));
}
__device__ __forceinline__ float lo_f(u64 v) {
    return __int_as_float(__double2loint(__longlong_as_double(v)));
}
__device__ __forceinline__ float hi_f(u64 v) {
    return __int_as_float(__double2hiint(__longlong_as_double(v)));
}
__device__ __forceinline__ int lo_i(u64 v) {
    return __double2loint(__longlong_as_double(v));
}
__device__ __forceinline__ int hi_i(u64 v) {
    return __double2hiint(__longlong_as_double(v));
}

// Slope-intercept LUT with zero pad bin 28 (beyond 19.6A cutoff -> exactly 0).
__device__ float2 g_lut[LUT_SIZE];
// Atoms bucket-sorted by type, coords pre-scaled by 1/0.7; j-side AoS view.
__device__ float4 g_atoms[N_ATOMS];
// i-side pair-packed view: per atom pair 8 floats [x0,x1,y0,y1,z0,z1,w0,w1].
__device__ double2 g_ipairs[N_ATOMS];
__device__ int    g_tij[NTILEPAIRS];              // tile b -> (ti<<8 | tj)
__device__ double   g_sums[NSLOTS];
__device__ unsigned g_count;
// Sort pipeline state — module-load zeroed; the last sort block re-zeros it
// every run, so every graph replay sees a clean state.
__device__ int      g_hist[NT];
__device__ int      g_cursor[NT];
__device__ unsigned g_histdone;
__device__ unsigned g_flag;
__device__ unsigned g_k2done;

// Fused prep: blocks [0, SORT_BLOCKS) run the sort pipeline (hist -> scan ->
// scatter -> self-clean); blocks [SORT_BLOCKS, PREP_GRID) build the LUT (4
// entries/thread), the tile decode table, and zero the accumulators.
// PREP_GRID=119 <= 148 SMs: every block is resident before any spin, so the
// intra-grid waits cannot deadlock.
__global__ void prep_kernel(const float* __restrict__ pot,
                            const float* __restrict__ coords,
                            const int*  __restrict__ res_ids,
                            const int*  __restrict__ type_indices) {
    int tid = threadIdx.x;

    if (blockIdx.x >= SORT_BLOCKS) {
        // ---------- LUT / tij / accumulator-zero role ----------
        int lb   = blockIdx.x - SORT_BLOCKS;
        int base = lb * 2048 + tid * 4;           // 4 consecutive entries (MLP 8)
        if (lb == 0 && tid <= NSLOTS) {
            if (tid < NSLOTS) g_sums[tid] = 0.0;
            else g_count = 0u;
        }
#pragma unroll
        for (int k = 0; k < 4; ++k) {
            int idx = base + k;
            if (idx < LUT_SIZE) {
                int t12 = idx / BINS2;
                int d   = idx - t12 * BINS2;
                float2 v;
                if (d >= BINS) {
                    v = make_float2(0.0f, 0.0f);  // pad bin
                } else {
                    float e0 = pot[t12 * BINS + d];
                    float e1 = (d == BINS - 1) ? e0 : pot[t12 * BINS + d + 1];
                    float B  = e1 - e0;
                    v = make_float2(fmaf(-(float)d, B, e0), B);
                }
                g_lut[idx] = v;
            }
        }
        int b = lb * 512 + tid;                   // tile decode table
        if (b < NTILEPAIRS) {
            int ti = 0, acc = 0;
            while (acc + (T_TILES - ti) <= b) { acc += T_TILES - ti; ++ti; }
            g_tij[b] = (ti << 8) | (ti + (b - acc));
        }
        return;
    }

    // ---------- sort role (blocks 0..15, one atom per thread) ----------
    __shared__ int sh[NT];
    int i = blockIdx.x * 512 + tid;
    int t = type_indices[i];

    for (int k = tid; k < NT; k += 512) sh[k] = 0;
    __syncthreads();
    atomicAdd(&sh[t], 1);
    __syncthreads();
    for (int k = tid; k < NT; k += 512)
        if (sh[k]) atomicAdd(&g_hist[k], sh[k]);
    __syncthreads();
    if (tid == 0) {
        __threadfence();
        atomicAdd(&g_histdone, 1u);
    }

    if (blockIdx.x == 0 && tid == 0) {            // scan after all hists land
        while (atomicAdd(&g_histdone, 0u) < SORT_BLOCKS) __nanosleep(32);
        // Plain .cg loads: L1 was never populated with these lines this launch
        // (atomics go straight to L2), histdone+fence orders the writes ->
        // values are coherent. Independent loads -> MLP-85, overlapped latency.
        int c[NT];
#pragma unroll
        for (int k = 0; k < NT; ++k) c[k] = __ldcg(&g_hist[k]);
        int run = 0;
        for (int k = 0; k < NT; ++k) { g_cursor[k] = run; run += c[k]; }
        __threadfence();
        atomicExch(&g_flag, 1u);
    }
    if (tid == 0) {
        while (atomicAdd(&g_flag, 0u) == 0u) __nanosleep(32);
    }
    __syncthreads();

    int pos = atomicAdd(&g_cursor[t], 1);         // L2 atomic: always coherent
    float x = coords[3 * i + 0] * INV07;
    float y = coords[3 * i + 1] * INV07;
    float z = coords[3 * i + 2] * INV07;
    int   w = (res_ids[i] << 18) | (t * ROWSZ2);
    g_atoms[pos] = make_float4(x, y, z, __int_as_float(w));
    float* f = (float*)g_ipairs;                  // pair-packed mirror
    int p = pos >> 1, s = pos & 1;
    f[8 * p + 0 + s] = x;
    f[8 * p + 2 + s] = y;
    f[8 * p + 4 + s] = z;
    f[8 * p + 6 + s] = __int_as_float(w);

    __syncthreads();
    if (tid == 0) {                               // last sort block cleans state
        unsigned done = atomicAdd(&g_k2done, 1u);
        if (done == SORT_BLOCKS - 1) {
            for (int k = 0; k < NT; ++k) g_hist[k] = 0;
            g_histdone = 0u;
            g_flag = 0u;
            g_k2done = 0u;
            __threadfence();
        }
    }
}

// 32 i atoms (16 packed pairs) vs this thread's j atom.
template <bool DIAG>
__device__ __forceinline__ float chunk_sum(const double2* __restrict__ ib,
                                           u64 jxn, u64 jyn, u64 jzn,
                                           int loB, const float2* __restrict__ jlut,
                                           int lim) {
    float acc0 = 0.0f, acc1 = 0.0f;
#pragma unroll
    for (int k = 0; k < 16; ++k) {
        double2 v0 = __ldg(&ib[2 * k + 0]);       // (x0x1, y0y1) uniform LDG.128
        double2 v1 = __ldg(&ib[2 * k + 1]);       // (z0z1, w0w1)
        u64 xs = __double_as_longlong(v0.x);
        u64 ys = __double_as_longlong(v0.y);
        u64 zs = __double_as_longlong(v1.x);
        u64 ws = __double_as_longlong(v1.y);

        u64 dx2, dy2, dz2, d2p;
        F32X2_ADD(dx2, xs, jxn);                  // (xi - xj) x2
        F32X2_ADD(dy2, ys, jyn);
        F32X2_ADD(dz2, zs, jzn);
        F32X2_MUL(d2p, dx2, dx2);
        F32X2_FMA(d2p, dy2, dy2, d2p);
        F32X2_FMA(d2p, dz2, dz2, d2p);            // (d/0.7)^2 for both pairs

        {   // pair 0 (i local = 2k); self-pair NaN routes to pad bin, masked out
            float d2 = lo_f(d2p);
            int   pi = lo_i(ws);
            float ds = d2 * rsqrtf(d2);
            float dsc = fminf(ds, 28.0f);         // NaN -> 28 -> (0,0) pad
            int   d0 = (int)dsc;
            float2 e = __ldg(&jlut[(pi & 0x3FFFF) + d0]);
            bool ok = (unsigned)(pi - loB) >= (5u << 18);   // sep > 2
            if (DIAG) ok &= (2 * k < lim);
            float val = fmaf(e.y, ds, e.x);
            if (ok) acc0 += val;
        }
        {   // pair 1 (i local = 2k+1)
            float d2 = hi_f(d2p);
            int   pi = hi_i(ws);
            float ds = d2 * rsqrtf(d2);
            float dsc = fminf(ds, 28.0f);
            int   d0 = (int)dsc;
            float2 e = __ldg(&jlut[(pi & 0x3FFFF) + d0]);
            bool ok = (unsigned)(pi - loB) >= (5u << 18);
            if (DIAG) ok &= (2 * k + 1 < lim);
            float val = fmaf(e.y, ds, e.x);
            if (ok) acc1 += val;
        }
    }
    return acc0 + acc1;
}

__global__ __launch_bounds__(THREADS, BLOCKS_PER_SM)
void dfire_kernel(float* __restrict__ out) {
    __shared__ double s_warp[THREADS / 32];
    const int tid = threadIdx.x;

    float acc = 0.0f;

    for (int u = blockIdx.x; u < NUNITS; u += GRID_PERSIST) {
        int b  = u >> 2;
        int q  = u & 3;
        int tt = g_tij[b];
        int ti = tt >> 8;
        int tj = tt & 255;

        const double2* ib = g_ipairs + (ti * TILE + q * 32);
        float4 aj = g_atoms[tj * TILE + tid];     // coalesced LDG.128

        int pj    = __float_as_int(aj.w);
        int jres  = pj >> 18;
        int jtype = (pj & 0x3FFFF) / ROWSZ2;
        int loB   = (jres - 2) << 18;
        const float2* jlut = g_lut + jtype * BINS2;
        u64 jxn = pack2(-aj.x, -aj.x);
        u64 jyn = pack2(-aj.y, -aj.y);
        u64 jzn = pack2(-aj.z, -aj.z);

        if (ti == tj) {
            int lim = tid - q * 32;               // i_local < j_local
            acc += chunk_sum<true >(ib, jxn, jyn, jzn, loB, jlut, lim);
        } else {
            acc += chunk_sum<false>(ib, jxn, jyn, jzn, loB, jlut, 0);
        }
    }

#pragma unroll
    for (int off = 16; off > 0; off >>= 1)
        acc += __shfl_xor_sync(0xFFFFFFFFu, acc, off);
    if ((tid & 31) == 0) s_warp[tid >> 5] = (double)acc;
    __syncthreads();

    if (tid == 0) {
        double s = s_warp[0] + s_warp[1] + s_warp[2] + s_warp[3];
        atomicAdd(&g_sums[blockIdx.x & (NSLOTS - 1)], s);
        __threadfence();
        unsigned done = atomicAdd(&g_count, 1u);
        if (done == GRID_PERSIST - 1) {           // last block finalizes
            double tot = 0.0;
#pragma unroll
            for (int k = 0; k < NSLOTS; ++k)
                tot += atomicAdd(&g_sums[k], 0.0);
            out[0] = (float)tot;
        }
    }
}

extern "C" void kernel_launch(void* const* d_in, const int* in_sizes, int n_in,
                              void* d_out, int out_size) {
    // Input order: coords, pot_tensor, res_ids, type_indices, i_idx, j_idx
    const float* coords       = (const float*)d_in[0];
    const float* pot_tensor   = (const float*)d_in[1];
    const int*   res_ids      = (const int*)d_in[2];
    const int*   type_indices = (const int*)d_in[3];
    // i_idx / j_idx are the deterministic triu indices; regenerated implicitly.
    (void)in_sizes; (void)n_in; (void)out_size;
    float* out = (float*)d_out;

    prep_kernel<<<PREP_GRID, 512>>>(pot_tensor, coords, res_ids, type_indices);
    dfire_kernel<<<GRID_PERSIST, THREADS>>>(out);
}